// round 2
// baseline (speedup 1.0000x reference)
#include <cuda_runtime.h>
#include <cuda_bf16.h>
#include <cstdint>

// Problem constants (fixed by the reference generator).
#define NN   4096      // nodes
#define BB   2048      // batch
#define LL   128       // latent
#define KK   16        // max fan-in
#define DW   145       // 1 + LL + KK  (weights row length)
#define GKK  129       // 1 + LL       (GEMM K dim)

#define NE      14     // batch elements per CTA (14 * 16388B = 229,432B smem <= 232,448 opt-in)
#define STRIDE  4097   // per-element smem stride in floats: bank = (t + p) mod 32 -> conflict-free

// ---------------------------------------------------------------------------
// Scratch (static __device__ allocation is allowed; zero-initialized at load,
// so the one-past-the-end prefetch rows read zeros, never garbage).
// ---------------------------------------------------------------------------
__device__ float        g_pre[(NN + 1) * BB];     // pre[i*BB + b] = bias + z[b].wz[i]
__device__ unsigned int g_meta[(NN + 1) * 32];    // per node: 16 parent idx (u32) + 16 wp (f32 bits)

// ---------------------------------------------------------------------------
// Kernel 1: pack per-node metadata into one 128B line per node.
// ---------------------------------------------------------------------------
__global__ void pack_meta_kernel(const float* __restrict__ w,
                                 const int*   __restrict__ par)
{
    int i = blockIdx.x;          // 0..NN-1
    int k = threadIdx.x;         // 0..31
    unsigned int v;
    if (k < 16)
        v = (unsigned int)par[i * KK + k];
    else
        v = __float_as_uint(w[i * DW + (1 + LL) + (k - 16)]);
    g_meta[i * 32 + k] = v;
}

// ---------------------------------------------------------------------------
// Kernel 2: pre[i][b] = sum_{k=0}^{128} w[i][k] * base[b][k],  base=[1, z].
// Classic 64x64 tile, 256 threads, 4x4 register blocking, full K in smem.
// ---------------------------------------------------------------------------
#define G_PAD 68   // padded leading dim to break store bank conflicts
__global__ void gemm_pre_kernel(const float* __restrict__ z,
                                const float* __restrict__ w)
{
    extern __shared__ float smg[];
    float* As = smg;                 // As[k*G_PAD + r] = w[i0+r][k]
    float* Zs = smg + GKK * G_PAD;   // Zs[k*G_PAD + c] = base[b0+c][k]

    const int i0 = blockIdx.y * 64;
    const int b0 = blockIdx.x * 64;
    const int tid = threadIdx.x;     // 256 threads

    for (int idx = tid; idx < 64 * GKK; idx += 256) {
        int r = idx / GKK, k = idx - r * GKK;
        As[k * G_PAD + r] = w[(i0 + r) * DW + k];
    }
    for (int idx = tid; idx < 64 * GKK; idx += 256) {
        int c = idx / GKK, k = idx - c * GKK;
        Zs[k * G_PAD + c] = (k == 0) ? 1.0f : z[(b0 + c) * LL + (k - 1)];
    }
    __syncthreads();

    const int tx = tid & 15;         // b sub-tile
    const int ty = tid >> 4;         // i sub-tile
    const int ri = ty * 4, ci = tx * 4;

    float acc[4][4];
#pragma unroll
    for (int r = 0; r < 4; r++)
#pragma unroll
        for (int c = 0; c < 4; c++) acc[r][c] = 0.0f;

#pragma unroll 3
    for (int k = 0; k < GKK; k++) {
        float4 a  = *reinterpret_cast<const float4*>(&As[k * G_PAD + ri]);
        float4 zc = *reinterpret_cast<const float4*>(&Zs[k * G_PAD + ci]);
        float av[4] = {a.x, a.y, a.z, a.w};
        float zv[4] = {zc.x, zc.y, zc.z, zc.w};
#pragma unroll
        for (int r = 0; r < 4; r++)
#pragma unroll
            for (int c = 0; c < 4; c++)
                acc[r][c] = fmaf(av[r], zv[c], acc[r][c]);
    }

#pragma unroll
    for (int r = 0; r < 4; r++) {
        float4 o = make_float4(acc[r][0], acc[r][1], acc[r][2], acc[r][3]);
        *reinterpret_cast<float4*>(&g_pre[(size_t)(i0 + ri + r) * BB + b0 + ci]) = o;
    }
}

// ---------------------------------------------------------------------------
// Kernel 3: the sequential DAG chain. One thread per batch element, chain
// state resident in SMEM (stride 4097 -> conflict-free indexed gathers).
// Metadata + pre are register-prefetched one node ahead.
// ---------------------------------------------------------------------------
__global__ void __launch_bounds__(128, 1)
chain_kernel(float* __restrict__ out)
{
    extern __shared__ float sm[];
    const int tid = threadIdx.x;

    // Zero chain state (node 0's gathers read u[0] with weight 0; must not be NaN).
    for (int j = tid; j < NE * STRIDE; j += blockDim.x) sm[j] = 0.0f;
    __syncthreads();

    if (tid < NE) {
        int b = blockIdx.x * NE + tid;
        if (b >= BB) b = BB - 1;                 // duplicate work, dump-skipped
        float* __restrict__ u = sm + tid * STRIDE;

        const int4*   mp = reinterpret_cast<const int4*>(g_meta);
        const float4* mw = reinterpret_cast<const float4*>(g_meta);

        // Prefetch node 0.
        int4   P0 = __ldg(mp + 0), P1 = __ldg(mp + 1), P2 = __ldg(mp + 2), P3 = __ldg(mp + 3);
        float4 W0 = __ldg(mw + 4), W1 = __ldg(mw + 5), W2 = __ldg(mw + 6), W3 = __ldg(mw + 7);
        float  prec = __ldg(g_pre + b);

#pragma unroll 1
        for (int i = 0; i < NN; i++) {
            // Prefetch node i+1 (arrays padded: i=NN-1 reads zeroed row NN).
            const int nb = (i + 1) * 8;
            int4   nP0 = __ldg(mp + nb + 0), nP1 = __ldg(mp + nb + 1);
            int4   nP2 = __ldg(mp + nb + 2), nP3 = __ldg(mp + nb + 3);
            float4 nW0 = __ldg(mw + nb + 4), nW1 = __ldg(mw + nb + 5);
            float4 nW2 = __ldg(mw + nb + 6), nW3 = __ldg(mw + nb + 7);
            float  pren = __ldg(g_pre + (size_t)(i + 1) * BB + b);

            // 16 conflict-free SMEM gathers, 4 accumulator chains.
            float a0 = u[P0.x] * W0.x;
            float a1 = u[P0.y] * W0.y;
            float a2 = u[P0.z] * W0.z;
            float a3 = u[P0.w] * W0.w;
            a0 = fmaf(u[P1.x], W1.x, a0);
            a1 = fmaf(u[P1.y], W1.y, a1);
            a2 = fmaf(u[P1.z], W1.z, a2);
            a3 = fmaf(u[P1.w], W1.w, a3);
            a0 = fmaf(u[P2.x], W2.x, a0);
            a1 = fmaf(u[P2.y], W2.y, a1);
            a2 = fmaf(u[P2.z], W2.z, a2);
            a3 = fmaf(u[P2.w], W2.w, a3);
            a0 = fmaf(u[P3.x], W3.x, a0);
            a1 = fmaf(u[P3.y], W3.y, a1);
            a2 = fmaf(u[P3.z], W3.z, a2);
            a3 = fmaf(u[P3.w], W3.w, a3);

            float s = prec + ((a0 + a1) + (a2 + a3));
            // tanh(s) = 1 - 2/(exp(2s)+1); exact at both saturation ends.
            float e = __expf(s + s);
            float r = __fdividef(2.0f, e + 1.0f);
            float t = fmaf(-1.0f, r, 1.0f);
            u[i] = t;

            P0 = nP0; P1 = nP1; P2 = nP2; P3 = nP3;
            W0 = nW0; W1 = nW1; W2 = nW2; W3 = nW3;
            prec = pren;
        }
    }
    __syncthreads();

    // Cooperative coalesced dump: SMEM -> out[b*NN + i].
    for (int e = 0; e < NE; e++) {
        const int b = blockIdx.x * NE + e;
        if (b >= BB) break;
        const float* __restrict__ us = sm + e * STRIDE;
        for (int j = tid; j < NN; j += blockDim.x)
            out[(size_t)b * NN + j] = us[j];
    }
}

// ---------------------------------------------------------------------------
// Launch. Inputs (metadata order): z f32[2048,128], weights f32[4096,145],
// parent_mask f32[4096,16] (redundant — weights are pre-masked), parents i32[4096,16].
// Output: f32[2048, 4096].
// ---------------------------------------------------------------------------
extern "C" void kernel_launch(void* const* d_in, const int* in_sizes, int n_in,
                              void* d_out, int out_size)
{
    const float* z       = (const float*)d_in[0];
    const float* weights = (const float*)d_in[1];
    const int*   parents = (const int*)d_in[3];
    float*       out     = (float*)d_out;

    const int gemm_smem  = 2 * GKK * G_PAD * (int)sizeof(float);     // 70,176 B
    const int chain_smem = NE * STRIDE * (int)sizeof(float);         // 229,432 B

    cudaFuncSetAttribute(gemm_pre_kernel,
                         cudaFuncAttributeMaxDynamicSharedMemorySize, gemm_smem);
    cudaFuncSetAttribute(chain_kernel,
                         cudaFuncAttributeMaxDynamicSharedMemorySize, chain_smem);

    pack_meta_kernel<<<NN, 32>>>(weights, parents);

    dim3 ggrid(BB / 64, NN / 64);
    gemm_pre_kernel<<<ggrid, 256, gemm_smem>>>(z, weights);

    const int nblocks = (BB + NE - 1) / NE;   // 147
    chain_kernel<<<nblocks, 128, chain_smem>>>(out);
}

// round 3
// speedup vs baseline: 1.8038x; 1.8038x over previous
#include <cuda_runtime.h>
#include <cuda_bf16.h>
#include <cstdint>

// Problem constants (fixed by the reference generator).
#define NN   4096      // nodes
#define BB   2048      // batch
#define LL   128       // latent
#define KK   16        // max fan-in
#define DW   145       // 1 + LL + KK  (weights row length)
#define GKK  129       // 1 + LL       (GEMM K dim)

#define NE      14     // batch elements per CTA (14 * 16388B = 229,432B smem)
#define STRIDE  4097   // per-element smem stride: bank = (t + p) mod 32 -> conflict-free

// ---------------------------------------------------------------------------
// Scratch (__device__ globals are zero-initialized at load; padded tail rows
// are never written, so prefetch overruns read zeros, never garbage).
// ---------------------------------------------------------------------------
__device__ float        g_pre[(NN + 8) * BB];     // pre[i*BB+b] = bias + z[b].wz[i]
__device__ unsigned int g_meta[(NN + 8) * 32];    // per node: 16 parent idx + 16 wp bits
__device__ float        g_wprev[NN + 8];          // sum of w over slots with parent==i-1

// ---------------------------------------------------------------------------
// Kernel 1: pack per-node metadata (one 128B line per node) + wprev.
// 256 threads = 8 nodes per block.
// ---------------------------------------------------------------------------
__global__ void pack_meta_kernel(const float* __restrict__ w,
                                 const int*   __restrict__ par)
{
    const int wid = threadIdx.x >> 5;
    const int k   = threadIdx.x & 31;
    const int i   = blockIdx.x * 8 + wid;
    if (i >= NN) return;

    unsigned int v;
    float pw = 0.0f;
    if (k < 16) {
        int p = par[i * KK + k];
        v = (unsigned int)p;
        float wk = w[i * DW + (1 + LL) + k];
        pw = (p == i - 1) ? wk : 0.0f;
    } else {
        v = __float_as_uint(w[i * DW + (1 + LL) + (k - 16)]);
    }
    g_meta[i * 32 + k] = v;

    // reduce pw over lanes 0..15 (lanes 16..31 contribute 0)
    #pragma unroll
    for (int off = 8; off > 0; off >>= 1)
        pw += __shfl_down_sync(0xffffffffu, pw, off);
    if (k == 0) g_wprev[i] = pw;
}

// ---------------------------------------------------------------------------
// Kernel 2: pre[i][b] = sum_{k=0}^{128} w[i][k] * base[b][k],  base=[1, z].
// 64x64 tile, 256 threads, 4x4 register blocking, full K in smem.
// ---------------------------------------------------------------------------
#define G_PAD 68
__global__ void gemm_pre_kernel(const float* __restrict__ z,
                                const float* __restrict__ w)
{
    extern __shared__ float smg[];
    float* As = smg;                 // As[k*G_PAD + r] = w[i0+r][k]
    float* Zs = smg + GKK * G_PAD;   // Zs[k*G_PAD + c] = base[b0+c][k]

    const int i0 = blockIdx.y * 64;
    const int b0 = blockIdx.x * 64;
    const int tid = threadIdx.x;

    for (int idx = tid; idx < 64 * GKK; idx += 256) {
        int r = idx / GKK, k = idx - r * GKK;
        As[k * G_PAD + r] = w[(i0 + r) * DW + k];
    }
    for (int idx = tid; idx < 64 * GKK; idx += 256) {
        int c = idx / GKK, k = idx - c * GKK;
        Zs[k * G_PAD + c] = (k == 0) ? 1.0f : z[(b0 + c) * LL + (k - 1)];
    }
    __syncthreads();

    const int tx = tid & 15;
    const int ty = tid >> 4;
    const int ri = ty * 4, ci = tx * 4;

    float acc[4][4];
#pragma unroll
    for (int r = 0; r < 4; r++)
#pragma unroll
        for (int c = 0; c < 4; c++) acc[r][c] = 0.0f;

#pragma unroll 3
    for (int k = 0; k < GKK; k++) {
        float4 a  = *reinterpret_cast<const float4*>(&As[k * G_PAD + ri]);
        float4 zc = *reinterpret_cast<const float4*>(&Zs[k * G_PAD + ci]);
        float av[4] = {a.x, a.y, a.z, a.w};
        float zv[4] = {zc.x, zc.y, zc.z, zc.w};
#pragma unroll
        for (int r = 0; r < 4; r++)
#pragma unroll
            for (int c = 0; c < 4; c++)
                acc[r][c] = fmaf(av[r], zv[c], acc[r][c]);
    }

#pragma unroll
    for (int r = 0; r < 4; r++) {
        float4 o = make_float4(acc[r][0], acc[r][1], acc[r][2], acc[r][3]);
        *reinterpret_cast<float4*>(&g_pre[(size_t)(i0 + ri + r) * BB + b0 + ci]) = o;
    }
}

// ---------------------------------------------------------------------------
// Kernel 3: sequential DAG chain. One thread per batch element, chain state
// in SMEM. Key trick: gathers for node m+1 are issued BEFORE u[m] is stored;
// the (parent==m) slot then reads a deterministic 0 (smem zeroed, each u[j]
// written once), and its contribution is restored next iteration via the
// precomputed wprev term: s += t_prev * wprev. This removes the
// tanh->STS->LDS->FMA-chain serial recurrence. Meta/pre are LDG-prefetched
// 4 nodes deep (statically indexed register buffers, loop unrolled x4).
// ---------------------------------------------------------------------------
__global__ void __launch_bounds__(128, 1)
chain_kernel(float* __restrict__ out)
{
    extern __shared__ float sm[];
    const int tid = threadIdx.x;

    for (int j = tid; j < NE * STRIDE; j += 128) sm[j] = 0.0f;
    __syncthreads();

    if (tid < NE) {
        int b = blockIdx.x * NE + tid;
        if (b >= BB) b = BB - 1;                 // duplicate work, dump-skipped
        float* __restrict__ u = sm + tid * STRIDE;

        const int4*   mp  = reinterpret_cast<const int4*>(g_meta);
        const float4* mwf = reinterpret_cast<const float4*>(g_meta);

        int4   Pb[4][4];
        float4 Wb[4][4];
        float  preb[4], wpb[4];
        float  g[16];

#pragma unroll
        for (int j = 0; j < 4; j++) {
#pragma unroll
            for (int q = 0; q < 4; q++) Pb[j][q] = __ldg(mp  + j * 8 + q);
#pragma unroll
            for (int q = 0; q < 4; q++) Wb[j][q] = __ldg(mwf + j * 8 + 4 + q);
            preb[j] = __ldg(g_pre + (size_t)j * BB + b);
            wpb[j]  = __ldg(g_wprev + j);
        }
#pragma unroll
        for (int k = 0; k < 16; k++) g[k] = 0.0f;   // node 0 gathers read u[0]=0

        float tprev = 0.0f;

#pragma unroll 1
        for (int base = 0; base < NN; base += 4) {
#pragma unroll
            for (int j = 0; j < 4; j++) {
                const int m = base + j;

                // 1. products + reduction (gathered values for node m)
                float a0 = fmaf(g[0],  Wb[j][0].x, preb[j]);
                float a1 = g[1]  * Wb[j][0].y;
                float a2 = g[2]  * Wb[j][0].z;
                float a3 = g[3]  * Wb[j][0].w;
                a0 = fmaf(g[4],  Wb[j][1].x, a0);
                a1 = fmaf(g[5],  Wb[j][1].y, a1);
                a2 = fmaf(g[6],  Wb[j][1].z, a2);
                a3 = fmaf(g[7],  Wb[j][1].w, a3);
                a0 = fmaf(g[8],  Wb[j][2].x, a0);
                a1 = fmaf(g[9],  Wb[j][2].y, a1);
                a2 = fmaf(g[10], Wb[j][2].z, a2);
                a3 = fmaf(g[11], Wb[j][2].w, a3);
                a0 = fmaf(g[12], Wb[j][3].x, a0);
                a1 = fmaf(g[13], Wb[j][3].y, a1);
                a2 = fmaf(g[14], Wb[j][3].z, a2);
                a3 = fmaf(g[15], Wb[j][3].w, a3);
                float s = (a0 + a1) + (a2 + a3);
                s = fmaf(tprev, wpb[j], s);          // patch for parent==m-1

                // 2. gathers for node m+1 (BEFORE storing u[m]; parent==m
                //    slot reads 0, restored next iter via wprev)
                {
                    const int jn = (j + 1) & 3;
                    int4 p0 = Pb[jn][0], p1 = Pb[jn][1];
                    int4 p2 = Pb[jn][2], p3 = Pb[jn][3];
                    g[0]  = u[p0.x]; g[1]  = u[p0.y]; g[2]  = u[p0.z]; g[3]  = u[p0.w];
                    g[4]  = u[p1.x]; g[5]  = u[p1.y]; g[6]  = u[p1.z]; g[7]  = u[p1.w];
                    g[8]  = u[p2.x]; g[9]  = u[p2.y]; g[10] = u[p2.z]; g[11] = u[p2.w];
                    g[12] = u[p3.x]; g[13] = u[p3.y]; g[14] = u[p3.z]; g[15] = u[p3.w];
                }

                // 3. tanh(s) = 1 - 2/(exp(2s)+1); saturates exactly at +-1
                float e, r;
                asm("ex2.approx.f32 %0, %1;" : "=f"(e) : "f"(s * 2.885390082f));
                asm("rcp.approx.f32 %0, %1;" : "=f"(r) : "f"(e + 1.0f));
                float t = fmaf(-2.0f, r, 1.0f);

                // 4. commit
                u[m] = t;
                tprev = t;

                // 5. prefetch meta for node m+4 into slot j (consumed ~3-4
                //    bodies later -> covers L2 latency)
                {
                    const size_t rf = (size_t)(m + 4) * 8;
#pragma unroll
                    for (int q = 0; q < 4; q++) Pb[j][q] = __ldg(mp  + rf + q);
#pragma unroll
                    for (int q = 0; q < 4; q++) Wb[j][q] = __ldg(mwf + rf + 4 + q);
                    preb[j] = __ldg(g_pre + (size_t)(m + 4) * BB + b);
                    wpb[j]  = __ldg(g_wprev + m + 4);
                }
            }
        }
    }
    __syncthreads();

    // Cooperative coalesced dump: SMEM -> out[b*NN + i].
    for (int e = 0; e < NE; e++) {
        const int b = blockIdx.x * NE + e;
        if (b >= BB) break;
        const float* __restrict__ us = sm + e * STRIDE;
        for (int j = tid; j < NN; j += 128)
            out[(size_t)b * NN + j] = us[j];
    }
}

// ---------------------------------------------------------------------------
// Launch. Inputs: z f32[2048,128], weights f32[4096,145],
// parent_mask f32[4096,16] (redundant — weights pre-masked), parents i32[4096,16].
// Output: f32[2048, 4096].
// ---------------------------------------------------------------------------
extern "C" void kernel_launch(void* const* d_in, const int* in_sizes, int n_in,
                              void* d_out, int out_size)
{
    const float* z       = (const float*)d_in[0];
    const float* weights = (const float*)d_in[1];
    const int*   parents = (const int*)d_in[3];
    float*       out     = (float*)d_out;

    const int gemm_smem  = 2 * GKK * G_PAD * (int)sizeof(float);     // 70,176 B
    const int chain_smem = NE * STRIDE * (int)sizeof(float);         // 229,432 B

    cudaFuncSetAttribute(gemm_pre_kernel,
                         cudaFuncAttributeMaxDynamicSharedMemorySize, gemm_smem);
    cudaFuncSetAttribute(chain_kernel,
                         cudaFuncAttributeMaxDynamicSharedMemorySize, chain_smem);

    pack_meta_kernel<<<(NN + 7) / 8, 256>>>(weights, parents);

    dim3 ggrid(BB / 64, NN / 64);
    gemm_pre_kernel<<<ggrid, 256, gemm_smem>>>(z, weights);

    const int nblocks = (BB + NE - 1) / NE;   // 147
    chain_kernel<<<nblocks, 128, chain_smem>>>(out);
}